// round 15
// baseline (speedup 1.0000x reference)
#include <cuda_runtime.h>
#include <cuda_fp16.h>
#include <math.h>
#include <stdint.h>

// ---------------- fixed shapes ----------------
#define TKN   4096
#define NB    2
#define LSEQ  2048
#define DM    4096
#define DXB   1024
#define DIN   4096
#define NH    32
#define HP    128
#define HN    128
#define PROJ  10272
#define CONVD 6144
#define INTERD 14336
#define NCH   16
#define NBLK  (NB*NCH*NH)

// ---------------- scratch ----------------
__device__ __half d_hnormh[TKN*DM];
__device__ float  d_zx[TKN*PROJ];
__device__ float  d_xbc[TKN*CONVD];
__device__ float  d_dt[TKN*NH];
__device__ float  d_av[TKN*NH];
__device__ float  d_cs[NBLK*128];
__device__ float  d_gm[NBLK];
__device__ float  d_states[(size_t)NBLK*HP*HN];
__device__ float  d_prev[(size_t)NBLK*HP*HN];
__device__ __half d_Ydh[TKN*DIN];
__device__ __half d_Yh[TKN*DIN];
__device__ float  d_h[TKN*DM];
__device__ __half d_h2h[TKN*DM];
__device__ __half d_uph[(size_t)TKN*INTERD];
// fp16 weights
__device__ __half d_win_h[(size_t)PROJ*DM];
__device__ __half d_wout_h[(size_t)DM*DIN];
__device__ __half d_gu_h[(size_t)2*INTERD*DM];   // row-interleaved gate/up
__device__ __half d_down_h[(size_t)DM*INTERD];

static __device__ __forceinline__ float tf32r(float x) {
    uint32_t u; asm("cvt.rna.tf32.f32 %0, %1;" : "=r"(u) : "f"(x));
    return __uint_as_float(u);
}

// ---------------- convert weights fp32 -> fp16 ----------------
__global__ void to_half_k(const float* __restrict__ src, __half* __restrict__ dst, int n4)
{
    int stride = gridDim.x * blockDim.x;
    for (int i = blockIdx.x*blockDim.x + threadIdx.x; i < n4; i += stride) {
        float4 v = reinterpret_cast<const float4*>(src)[i];
        reinterpret_cast<__half2*>(dst)[2*i]   = __floats2half2_rn(v.x, v.y);
        reinterpret_cast<__half2*>(dst)[2*i+1] = __floats2half2_rn(v.z, v.w);
    }
}

// ---------------- interleave gate/up rows -> fp16 (even=gate, odd=up) ----------------
__global__ void interleave_half_k(const float* __restrict__ g, const float* __restrict__ u,
                                  __half* __restrict__ dst, int n4)
{
    int stride = gridDim.x * blockDim.x;
    for (int i = blockIdx.x*blockDim.x + threadIdx.x; i < n4; i += stride) {
        int r  = i >> 10;             // DM/4 = 1024 float4 per row
        int c4 = i & 1023;
        const float* src = ((r & 1) ? u : g) + (size_t)(r >> 1)*DM + c4*4;
        float4 v = *reinterpret_cast<const float4*>(src);
        __half* drow = dst + (size_t)r*DM + c4*4;
        *reinterpret_cast<__half2*>(drow)     = __floats2half2_rn(v.x, v.y);
        *reinterpret_cast<__half2*>(drow + 2) = __floats2half2_rn(v.z, v.w);
    }
}

// ---------- tf32 mma tile helpers (SSD path, proven) ----------
static __device__ __forceinline__ uint32_t swaddr(uint32_t base, int r, int c) {
    uint32_t sub   = (uint32_t)((c >> 5) << 14);
    uint32_t chunk = (uint32_t)(((((c & 31) >> 2)) ^ (r & 7)) << 4);
    uint32_t byte  = (uint32_t)((c & 3) << 2);
    return base + sub + (uint32_t)(r << 7) + chunk + byte;
}
static __device__ __forceinline__ void load_tile128(uint32_t sb, const float* g,
                                                    int grs, int tid) {
    #pragma unroll
    for (int i = 0; i < 16; i++) {
        int idx = i*256 + tid;
        int r = idx >> 5, c = (idx & 31) << 2;
        asm volatile("cp.async.cg.shared.global [%0], [%1], 16;"
                     :: "r"(swaddr(sb, r, c)), "l"(g + (size_t)r*grs + c));
    }
}
static __device__ __forceinline__ void mma_tile128(uint32_t abase, uint32_t bbase,
                                                   float (&acc)[4][4][4],
                                                   int wm, int wn, int lane) {
    #pragma unroll
    for (int t = 0; t < 4; t++) {
        uint32_t as = abase + (uint32_t)(t << 14), bs = bbase + (uint32_t)(t << 14);
        #pragma unroll
        for (int kk = 0; kk < 4; kk++) {
            uint32_t af[4][4];
            #pragma unroll
            for (int mt = 0; mt < 4; mt++) {
                int m  = wm*64 + mt*16 + (lane & 7) + ((lane >> 3) & 1) * 8;
                int kc = kk*2 + (lane >> 4);
                uint32_t addr = as + (uint32_t)(m << 7) + (uint32_t)((kc ^ (m & 7)) << 4);
                asm volatile("ldmatrix.sync.aligned.m8n8.x4.shared.b16 {%0,%1,%2,%3}, [%4];"
                             : "=r"(af[mt][0]), "=r"(af[mt][1]),
                               "=r"(af[mt][2]), "=r"(af[mt][3]) : "r"(addr));
            }
            #pragma unroll
            for (int nt = 0; nt < 4; nt++) {
                int nrow = wn*32 + nt*8 + (lane & 7);
                int bc = kk*2 + ((lane >> 3) & 1);
                uint32_t baddr = bs + (uint32_t)(nrow << 7) + (uint32_t)((bc ^ (nrow & 7)) << 4);
                uint32_t b0, b1;
                asm volatile("ldmatrix.sync.aligned.m8n8.x2.shared.b16 {%0,%1}, [%2];"
                             : "=r"(b0), "=r"(b1) : "r"(baddr));
                #pragma unroll
                for (int mt = 0; mt < 4; mt++) {
                    asm volatile(
                        "mma.sync.aligned.m16n8k8.row.col.f32.tf32.tf32.f32 "
                        "{%0,%1,%2,%3}, {%4,%5,%6,%7}, {%8,%9}, {%0,%1,%2,%3};"
                        : "+f"(acc[mt][nt][0]), "+f"(acc[mt][nt][1]),
                          "+f"(acc[mt][nt][2]), "+f"(acc[mt][nt][3])
                        : "r"(af[mt][0]), "r"(af[mt][1]), "r"(af[mt][2]), "r"(af[mt][3]),
                          "r"(b0), "r"(b1));
                }
            }
        }
    }
}
static __device__ __forceinline__ void transpose128(uint32_t src, uint32_t dst,
                                                    int warp, int lane) {
    #pragma unroll
    for (int ks = 0; ks < 4; ks++) {
        int k = ks*32 + lane;
        #pragma unroll
        for (int j = 0; j < 16; j++) {
            int p = warp*16 + j;
            float v;
            asm volatile("ld.shared.f32 %0, [%1];" : "=f"(v) : "r"(swaddr(src, k, p)));
            asm volatile("st.shared.f32 [%0], %1;" :: "r"(swaddr(dst, p, k)), "f"(v));
        }
    }
}
static __device__ __forceinline__ void zero_acc(float (&acc)[4][4][4]) {
    #pragma unroll
    for (int a = 0; a < 4; a++)
        #pragma unroll
        for (int b = 0; b < 4; b++)
            #pragma unroll
            for (int c = 0; c < 4; c++) acc[a][b][c] = 0.f;
}

// ================= fp16 mma.sync dense GEMM (128x128, 2 CTA/SM) =================
#define GSTAGE 32768
#define GSMEM_DYN (3*GSTAGE)
#define GROUP_M 16

__global__ void __launch_bounds__(256, 2)
gemm_h(const __half* __restrict__ A, const __half* __restrict__ Bw,
       const float* __restrict__ Res, float* __restrict__ Cf,
       __half* __restrict__ Ch, int N, int K, int mode)
{
    extern __shared__ char smraw[];
    const int tid  = threadIdx.x;
    const int lane = tid & 31, warp = tid >> 5;
    const int wm = warp & 1, wn = warp >> 1;
    const int T = K >> 6;
    uint32_t sbase = (uint32_t)__cvta_generic_to_shared(smraw);

    const int num_pid_n = (N + 127) >> 7;
    int pid = blockIdx.x;
    int npg = GROUP_M * num_pid_n;
    int pid_m = (pid / npg) * GROUP_M + (pid % GROUP_M);
    int pid_n = (pid % npg) / GROUP_M;
    const int bm = pid_m << 7, bn = pid_n << 7;

    auto load_tile = [&](int t) {
        uint32_t s = sbase + (uint32_t)(t % 3) * GSTAGE;
        int k0 = t << 6;
        #pragma unroll
        for (int i = 0; i < 4; i++) {
            int idx = i*256 + tid, row = idx >> 3, c = idx & 7;
            uint32_t dst = s + row*128 + (uint32_t)((c ^ (row & 7)) << 4);
            asm volatile("cp.async.cg.shared.global [%0], [%1], 16;"
                         :: "r"(dst), "l"(A + (size_t)(bm + row)*K + k0 + c*8));
        }
        #pragma unroll
        for (int i = 0; i < 4; i++) {
            int idx = i*256 + tid, row = idx >> 3, c = idx & 7;
            int brow = bn + row; if (brow >= N) brow = N - 1;
            uint32_t dst = s + 16384u + row*128 + (uint32_t)((c ^ (row & 7)) << 4);
            asm volatile("cp.async.cg.shared.global [%0], [%1], 16;"
                         :: "r"(dst), "l"(Bw + (size_t)brow*K + k0 + c*8));
        }
    };

    float acc[4][4][4];
    zero_acc(acc);

    load_tile(0);
    asm volatile("cp.async.commit_group;" ::: "memory");
    load_tile(1);
    asm volatile("cp.async.commit_group;" ::: "memory");

    for (int t = 0; t < T; t++) {
        asm volatile("cp.async.wait_group 1;" ::: "memory");
        __syncthreads();
        if (t + 2 < T) load_tile(t + 2);
        asm volatile("cp.async.commit_group;" ::: "memory");

        uint32_t as = sbase + (uint32_t)(t % 3) * GSTAGE;
        uint32_t bs = as + 16384u;

        #pragma unroll
        for (int kk = 0; kk < 4; kk++) {
            uint32_t af[4][4];
            #pragma unroll
            for (int mt = 0; mt < 4; mt++) {
                int m  = wm*64 + mt*16 + (lane & 7) + ((lane >> 3) & 1) * 8;
                int kc = kk*2 + (lane >> 4);
                uint32_t addr = as + m*128 + (uint32_t)((kc ^ (m & 7)) << 4);
                asm volatile("ldmatrix.sync.aligned.m8n8.x4.shared.b16 {%0,%1,%2,%3}, [%4];"
                             : "=r"(af[mt][0]), "=r"(af[mt][1]),
                               "=r"(af[mt][2]), "=r"(af[mt][3]) : "r"(addr));
            }
            #pragma unroll
            for (int np = 0; np < 2; np++) {
                int ntl  = np*2 + ((lane >> 4) & 1);
                int nrow = wn*32 + ntl*8 + (lane & 7);
                int bc   = kk*2 + ((lane >> 3) & 1);
                uint32_t baddr = bs + nrow*128 + (uint32_t)((bc ^ (nrow & 7)) << 4);
                uint32_t b0, b1, b2, b3;
                asm volatile("ldmatrix.sync.aligned.m8n8.x4.shared.b16 {%0,%1,%2,%3}, [%4];"
                             : "=r"(b0), "=r"(b1), "=r"(b2), "=r"(b3) : "r"(baddr));
                #pragma unroll
                for (int mt = 0; mt < 4; mt++) {
                    asm volatile(
                        "mma.sync.aligned.m16n8k16.row.col.f32.f16.f16.f32 "
                        "{%0,%1,%2,%3}, {%4,%5,%6,%7}, {%8,%9}, {%0,%1,%2,%3};"
                        : "+f"(acc[mt][np*2][0]), "+f"(acc[mt][np*2][1]),
                          "+f"(acc[mt][np*2][2]), "+f"(acc[mt][np*2][3])
                        : "r"(af[mt][0]), "r"(af[mt][1]), "r"(af[mt][2]), "r"(af[mt][3]),
                          "r"(b0), "r"(b1));
                }
                #pragma unroll
                for (int mt = 0; mt < 4; mt++) {
                    asm volatile(
                        "mma.sync.aligned.m16n8k16.row.col.f32.f16.f16.f32 "
                        "{%0,%1,%2,%3}, {%4,%5,%6,%7}, {%8,%9}, {%0,%1,%2,%3};"
                        : "+f"(acc[mt][np*2+1][0]), "+f"(acc[mt][np*2+1][1]),
                          "+f"(acc[mt][np*2+1][2]), "+f"(acc[mt][np*2+1][3])
                        : "r"(af[mt][0]), "r"(af[mt][1]), "r"(af[mt][2]), "r"(af[mt][3]),
                          "r"(b2), "r"(b3));
                }
            }
        }
    }

    // epilogue
    #pragma unroll
    for (int mt = 0; mt < 4; mt++) {
        int r0 = bm + wm*64 + mt*16 + (lane >> 2);
        #pragma unroll
        for (int nt = 0; nt < 4; nt++) {
            int c0 = bn + wn*32 + nt*8 + 2*(lane & 3);
            if (c0 < N) {
                float2 v0 = make_float2(acc[mt][nt][0], acc[mt][nt][1]);
                float2 v1 = make_float2(acc[mt][nt][2], acc[mt][nt][3]);
                if (mode == 3) {
                    float r0v = v0.y * (v0.x / (1.f + expf(-v0.x)));
                    float r1v = v1.y * (v1.x / (1.f + expf(-v1.x)));
                    int half_n = N >> 1;
                    Ch[(size_t)r0*half_n + (c0 >> 1)]     = __float2half_rn(r0v);
                    Ch[(size_t)(r0+8)*half_n + (c0 >> 1)] = __float2half_rn(r1v);
                } else {
                    if (mode == 1) {
                        float2 q0 = *reinterpret_cast<const float2*>(Res + (size_t)r0*N + c0);
                        float2 q1 = *reinterpret_cast<const float2*>(Res + (size_t)(r0+8)*N + c0);
                        v0.x += q0.x; v0.y += q0.y; v1.x += q1.x; v1.y += q1.y;
                    }
                    *reinterpret_cast<float2*>(Cf + (size_t)r0*N + c0)     = v0;
                    *reinterpret_cast<float2*>(Cf + (size_t)(r0+8)*N + c0) = v1;
                }
            }
        }
    }
}

static inline int gemm_grid(int N) { return 32 * ((N + 127) >> 7); }

// ---------------- RMSNorm (fp16 output) ----------------
__global__ void rmsnorm_k(const float* __restrict__ x, const float* __restrict__ w,
                          __half* __restrict__ o)
{
    int t = blockIdx.x;
    const float* xr = x + (size_t)t*DM;
    float s = 0.f;
    for (int i = threadIdx.x; i < DM; i += 256) { float v = xr[i]; s += v*v; }
    __shared__ float red[256];
    red[threadIdx.x] = s; __syncthreads();
    for (int st = 128; st > 0; st >>= 1) {
        if (threadIdx.x < st) red[threadIdx.x] += red[threadIdx.x + st];
        __syncthreads();
    }
    float inv = rsqrtf(red[0] / (float)DM + 1e-5f);
    __half* orow = o + (size_t)t*DM;
    for (int i = threadIdx.x; i < DM; i += 256) orow[i] = __float2half_rn(xr[i]*inv*w[i]);
}

// ---------------- fused conv+SiLU (tf32 out) and dt ----------------
__global__ void convdt_k(const float* __restrict__ zx, const float* __restrict__ cw,
                         const float* __restrict__ cb, const float* __restrict__ dtb,
                         const float* __restrict__ Alog,
                         float* __restrict__ xbc, float* __restrict__ dto,
                         float* __restrict__ ao)
{
    int t = blockIdx.y;
    if (blockIdx.x < 24) {
        int c = blockIdx.x*256 + threadIdx.x;
        int l = t & (LSEQ - 1);
        const float* base = zx + (size_t)t*PROJ + 4096 + c;
        float w0 = cw[c*4+0], w1 = cw[c*4+1], w2 = cw[c*4+2], w3 = cw[c*4+3];
        float acc = cb[c] + w3*base[0];
        if (l >= 1) acc += w2*base[-(ptrdiff_t)PROJ];
        if (l >= 2) acc += w1*base[-(ptrdiff_t)(2*PROJ)];
        if (l >= 3) acc += w0*base[-(ptrdiff_t)(3*PROJ)];
        float sv = acc / (1.f + expf(-acc));
        xbc[(size_t)t*CONVD + c] = tf32r(sv);
    } else if (threadIdx.x < NH) {
        int h = threadIdx.x;
        float raw = zx[(size_t)t*PROJ + 10240 + h] + dtb[h];
        float dt = (raw > 20.f) ? raw : log1pf(expf(raw));
        dto[t*NH + h] = dt;
        ao[t*NH + h]  = -expf(Alog[h]) * dt;
    }
}

// ---------------- SSD stage 1 (tf32 tensor cores) ----------------
#define SSD1_SMEM 196608
__global__ void __launch_bounds__(256)
ssd1_k(const float* __restrict__ xbc, const float* __restrict__ dtv,
       const float* __restrict__ av, const float* __restrict__ Dv,
       __half* __restrict__ Yd, float* __restrict__ cso,
       float* __restrict__ gmo, float* __restrict__ states)
{
    extern __shared__ float dyn[];
    __shared__ float cs[128], dts[128], wv[128], wsum[4];
    uint32_t sb = (uint32_t)__cvta_generic_to_shared(dyn);
    uint32_t O_C = sb, O_B = sb + 65536u, O_X = sb + 131072u;

    int blk = blockIdx.x;
    int h = blk & 31, ch = (blk >> 5) & 15, b = blk >> 9;
    int t0 = b*LSEQ + ch*128;
    int g  = h >> 2;
    int tid = threadIdx.x, lane = tid & 31, warp = tid >> 5;
    int wm = warp & 1, wn = warp >> 1;

    const float* gC = xbc + (size_t)t0*CONVD + 2048 + h*128;
    const float* gB = xbc + (size_t)t0*CONVD + 1024 + g*128;
    const float* gX = xbc + (size_t)t0*CONVD + g*128;
    load_tile128(O_C, gC, CONVD, tid);
    load_tile128(O_B, gB, CONVD, tid);
    load_tile128(O_X, gX, CONVD, tid);
    asm volatile("cp.async.commit_group;" ::: "memory");

    float v = 0.f;
    if (tid < 128) {
        dts[tid] = dtv[(size_t)(t0+tid)*NH + h];
        v = av[(size_t)(t0+tid)*NH + h];
        #pragma unroll
        for (int off = 1; off < 32; off <<= 1) {
            float n = __shfl_up_sync(0xffffffffu, v, off);
            if (lane >= off) v += n;
        }
        if (lane == 31) wsum[tid >> 5] = v;
    }
    __syncthreads();
    if (tid < 128) {
        float add = 0.f;
        for (int w = 0; w < (tid >> 5); w++) add += wsum[w];
        float c = v + add;
        cs[tid] = c;
        cso[blk*128 + tid] = c;
    }
    __syncthreads();
    if (tid < 128) wv[tid] = __expf(cs[127] - cs[tid]) * dts[tid];
    if (tid == 0) gmo[blk] = expf(cs[127]);

    asm volatile("cp.async.wait_group 0;" ::: "memory");
    __syncthreads();

    float acc[4][4][4];
    zero_acc(acc);
    mma_tile128(O_C, O_B, acc, wm, wn, lane);
    __syncthreads();
    transpose128(O_X, O_C, warp, lane);
    __syncthreads();
    #pragma unroll
    for (int mt = 0; mt < 4; mt++) {
        int r0 = wm*64 + mt*16 + (lane >> 2);
        #pragma unroll
        for (int nt = 0; nt < 4; nt++) {
            int c0 = wn*32 + nt*8 + 2*(lane & 3);
            #pragma unroll
            for (int e = 0; e < 4; e++) {
                int q = r0 + (e >> 1)*8, k = c0 + (e & 1);
                float f = (q >= k) ? __expf(cs[q] - cs[k]) * dts[k] : 0.f;
                float val = tf32r(acc[mt][nt][e] * f);
                asm volatile("st.shared.f32 [%0], %1;" :: "r"(swaddr(O_X, q, k)), "f"(val));
            }
        }
    }
    __syncthreads();
    zero_acc(acc);
    mma_tile128(O_X, O_C, acc, wm, wn, lane);
    float Dh = Dv[h];
    #pragma unroll
    for (int mt = 0; mt < 4; mt++) {
        int r0 = wm*64 + mt*16 + (lane >> 2);
        #pragma unroll
        for (int nt = 0; nt < 4; nt++) {
            int c0 = wn*32 + nt*8 + 2*(lane & 3);
            #pragma unroll
            for (int e = 0; e < 4; e++) {
                int q = r0 + (e >> 1)*8, p = c0 + (e & 1);
                float xv;
                asm volatile("ld.shared.f32 %0, [%1];" : "=f"(xv) : "r"(swaddr(O_C, p, q)));
                Yd[(size_t)(t0+q)*DIN + h*128 + p] = __float2half_rn(acc[mt][nt][e] + Dh*xv);
            }
        }
    }
    __syncthreads();
    transpose128(O_B, O_X, warp, lane);
    #pragma unroll
    for (int ks = 0; ks < 4; ks++) {
        int k = ks*32 + lane;
        float wk = wv[k];
        #pragma unroll
        for (int j = 0; j < 16; j++) {
            int p = warp*16 + j;
            float xv;
            asm volatile("ld.shared.f32 %0, [%1];" : "=f"(xv) : "r"(swaddr(O_C, p, k)));
            xv = tf32r(xv * wk);
            asm volatile("st.shared.f32 [%0], %1;" :: "r"(swaddr(O_C, p, k)), "f"(xv));
        }
    }
    __syncthreads();
    zero_acc(acc);
    mma_tile128(O_C, O_X, acc, wm, wn, lane);
    size_t sbase = (size_t)blk*HP*HN;
    #pragma unroll
    for (int mt = 0; mt < 4; mt++) {
        int r0 = wm*64 + mt*16 + (lane >> 2);
        #pragma unroll
        for (int nt = 0; nt < 4; nt++) {
            int c0 = wn*32 + nt*8 + 2*(lane & 3);
            *reinterpret_cast<float2*>(states + sbase + (size_t)r0*HN + c0)
                = make_float2(acc[mt][nt][0], acc[mt][nt][1]);
            *reinterpret_cast<float2*>(states + sbase + (size_t)(r0+8)*HN + c0)
                = make_float2(acc[mt][nt][2], acc[mt][nt][3]);
        }
    }
}

// ---------------- inter-chunk recurrence ----------------
__global__ void scan_k(const float* __restrict__ states, const float* __restrict__ gm,
                       float* __restrict__ prev)
{
    int bh = blockIdx.x;
    int b = bh >> 5, h = bh & 31;
    int e0 = threadIdx.x;
    float S[16];
    #pragma unroll
    for (int e = 0; e < 16; e++) S[e] = 0.f;
    for (int ch = 0; ch < NCH; ch++) {
        int blk = (b*NCH + ch)*NH + h;
        float gv = gm[blk];
        size_t base = (size_t)blk*HP*HN;
        #pragma unroll
        for (int e = 0; e < 16; e++) {
            int idx = e0 + e*1024;
            prev[base + idx] = tf32r(S[e]);
            S[e] = gv*S[e] + states[base + idx];
        }
    }
}

// ---------------- SSD stage 2 (tf32 tensor cores) + gating -> fp16 Yh ----------------
#define SSD2_SMEM 131072
__global__ void __launch_bounds__(256)
ssd2_k(const float* __restrict__ xbc, const float* __restrict__ prev,
       const float* __restrict__ csv, const float* __restrict__ zx,
       const __half* __restrict__ Yd, __half* __restrict__ Yh)
{
    extern __shared__ float dyn[];
    __shared__ float cs[128];
    uint32_t sb = (uint32_t)__cvta_generic_to_shared(dyn);
    uint32_t O_C = sb, O_P = sb + 65536u;

    int blk = blockIdx.x;
    int h = blk & 31, ch = (blk >> 5) & 15, b = blk >> 9;
    int t0 = b*LSEQ + ch*128;
    int tid = threadIdx.x, lane = tid & 31, warp = tid >> 5;
    int wm = warp & 1, wn = warp >> 1;

    const float* gC = xbc + (size_t)t0*CONVD + 2048 + h*128;
    size_t pbase = (size_t)blk*HP*HN;
    load_tile128(O_C, gC, CONVD, tid);
    load_tile128(O_P, prev + pbase, HN, tid);
    asm volatile("cp.async.commit_group;" ::: "memory");
    if (tid < 128) cs[tid] = csv[blk*128 + tid];
    asm volatile("cp.async.wait_group 0;" ::: "memory");
    __syncthreads();

    float acc[4][4][4];
    zero_acc(acc);
    mma_tile128(O_C, O_P, acc, wm, wn, lane);

    #pragma unroll
    for (int mt = 0; mt < 4; mt++) {
        int r0 = wm*64 + mt*16 + (lane >> 2);
        float eq0 = __expf(cs[r0]), eq1 = __expf(cs[r0 + 8]);
        #pragma unroll
        for (int nt = 0; nt < 4; nt++) {
            int c0 = wn*32 + nt*8 + 2*(lane & 3);
            #pragma unroll
            for (int half = 0; half < 2; half++) {
                int q = r0 + half*8;
                float eq = half ? eq1 : eq0;
                size_t off = (size_t)(t0+q)*DIN + h*128 + c0;
                __half2 ydh = *reinterpret_cast<const __half2*>(Yd + off);
                float2 yv = __half22float2(ydh);
                float2 zv = *reinterpret_cast<const float2*>(zx + (size_t)(t0+q)*PROJ + h*128 + c0);
                float s0 = zv.x / (1.f + expf(-zv.x));
                float s1 = zv.y / (1.f + expf(-zv.y));
                float a0 = acc[mt][nt][half*2+0], a1 = acc[mt][nt][half*2+1];
                *reinterpret_cast<__half2*>(Yh + off)
                    = __floats2half2_rn((yv.x + eq*a0) * s0, (yv.y + eq*a1) * s1);
            }
        }
    }
}

// ---------------- launcher ----------------
extern "C" void kernel_launch(void* const* d_in, const int* in_sizes, int n_in,
                              void* d_out, int out_size)
{
    const float* hidden = (const float*)d_in[0];
    const float* w_in   = (const float*)d_in[1];
    const float* conv_w = (const float*)d_in[2];
    const float* conv_b = (const float*)d_in[3];
    const float* A_log  = (const float*)d_in[4];
    const float* Dv     = (const float*)d_in[5];
    const float* dt_b   = (const float*)d_in[6];
    const float* w_out  = (const float*)d_in[7];
    const float* ln1    = (const float*)d_in[8];
    const float* ln2    = (const float*)d_in[9];
    const float* gate_w = (const float*)d_in[10];
    const float* up_w   = (const float*)d_in[11];
    const float* down_w = (const float*)d_in[12];
    float* out = (float*)d_out;

    float *zx, *xbc, *dt, *av, *cs, *gm, *st, *pv, *h;
    __half *hnormh, *Ydh, *Yh, *h2h, *uph;
    __half *winh, *wouth, *guh, *downh;
    cudaGetSymbolAddress((void**)&hnormh, d_hnormh);
    cudaGetSymbolAddress((void**)&zx,     d_zx);
    cudaGetSymbolAddress((void**)&xbc,    d_xbc);
    cudaGetSymbolAddress((void**)&dt,     d_dt);
    cudaGetSymbolAddress((void**)&av,     d_av);
    cudaGetSymbolAddress((void**)&cs,     d_cs);
    cudaGetSymbolAddress((void**)&gm,     d_gm);
    cudaGetSymbolAddress((void**)&st,     d_states);
    cudaGetSymbolAddress((void**)&pv,     d_prev);
    cudaGetSymbolAddress((void**)&Ydh,    d_Ydh);
    cudaGetSymbolAddress((void**)&Yh,     d_Yh);
    cudaGetSymbolAddress((void**)&h,      d_h);
    cudaGetSymbolAddress((void**)&h2h,    d_h2h);
    cudaGetSymbolAddress((void**)&uph,    d_uph);
    cudaGetSymbolAddress((void**)&winh,   d_win_h);
    cudaGetSymbolAddress((void**)&wouth,  d_wout_h);
    cudaGetSymbolAddress((void**)&guh,    d_gu_h);
    cudaGetSymbolAddress((void**)&downh,  d_down_h);

    cudaFuncSetAttribute(gemm_h, cudaFuncAttributeMaxDynamicSharedMemorySize, GSMEM_DYN);
    cudaFuncSetAttribute(ssd1_k, cudaFuncAttributeMaxDynamicSharedMemorySize, SSD1_SMEM);
    cudaFuncSetAttribute(ssd2_k, cudaFuncAttributeMaxDynamicSharedMemorySize, SSD2_SMEM);

    // one-time side stream + events
    static cudaStream_t s2 = nullptr;
    static cudaEvent_t e_fork = nullptr, e_win = nullptr, e_join = nullptr;
    static bool side_ok = false;
    if (!s2) {
        side_ok = (cudaStreamCreateWithFlags(&s2, cudaStreamNonBlocking) == cudaSuccess)
               && (cudaEventCreateWithFlags(&e_fork, cudaEventDisableTiming) == cudaSuccess)
               && (cudaEventCreateWithFlags(&e_win,  cudaEventDisableTiming) == cudaSuccess)
               && (cudaEventCreateWithFlags(&e_join, cudaEventDisableTiming) == cudaSuccess);
    }

    if (side_ok) {
        // side stream: all weight converts; w_in first (overlaps rmsnorm on main)
        cudaEventRecord(e_fork, 0);
        cudaStreamWaitEvent(s2, e_fork, 0);
        to_half_k<<<1024, 256, 0, s2>>>(w_in, winh, (PROJ*DM)/4);
        cudaEventRecord(e_win, s2);
        to_half_k<<<1024, 256, 0, s2>>>(w_out,  wouth, (DM*DIN)/4);
        interleave_half_k<<<2048, 256, 0, s2>>>(gate_w, up_w, guh, (2*INTERD*DM)/4);
        to_half_k<<<1024, 256, 0, s2>>>(down_w, downh, (DM*INTERD)/4);
        cudaEventRecord(e_join, s2);
        // main: pre-norm concurrent with w_in convert
        rmsnorm_k<<<TKN, 256>>>(hidden, ln1, hnormh);
        cudaStreamWaitEvent(0, e_win, 0);
    } else {
        to_half_k<<<1024, 256>>>(w_in,   winh,  (PROJ*DM)/4);
        to_half_k<<<1024, 256>>>(w_out,  wouth, (DM*DIN)/4);
        interleave_half_k<<<2048, 256>>>(gate_w, up_w, guh, (2*INTERD*DM)/4);
        to_half_k<<<1024, 256>>>(down_w, downh, (DM*INTERD)/4);
        rmsnorm_k<<<TKN, 256>>>(hidden, ln1, hnormh);
    }

    // 2) in_proj
    gemm_h<<<gemm_grid(PROJ), 256, GSMEM_DYN>>>(hnormh, winh, nullptr, zx, nullptr, PROJ, DM, 0);
    // 3+4) fused conv + dt
    convdt_k<<<dim3(25, TKN), 256>>>(zx, conv_w, conv_b, dt_b, A_log, xbc, dt, av);
    // 5) SSD stage 1 (tf32 tensor cores) -> Yd fp16
    ssd1_k<<<NBLK, 256, SSD1_SMEM>>>(xbc, dt, av, Dv, Ydh, cs, gm, st);
    // 6) inter-chunk recurrence
    scan_k<<<NB*NH, 1024>>>(st, gm, pv);
    // 7) SSD stage 2 + gating -> fp16 Yh
    ssd2_k<<<NBLK, 256, SSD2_SMEM>>>(xbc, pv, cs, zx, Ydh, Yh);

    // join: side-stream converts must be done before out_proj / MLP
    if (side_ok) cudaStreamWaitEvent(0, e_join, 0);

    // 8) out_proj + residual
    gemm_h<<<gemm_grid(DM), 256, GSMEM_DYN>>>(Yh, wouth, hidden, h, nullptr, DM, DIN, 1);
    // 9) second norm (fp16 output)
    rmsnorm_k<<<TKN, 256>>>(h, ln2, h2h);
    // 10) fused gate+up GEMM -> uph = silu(gate)*up (fp16)
    gemm_h<<<gemm_grid(2*INTERD), 256, GSMEM_DYN>>>(h2h, guh, nullptr, nullptr, uph,
                                                    2*INTERD, DM, 3);
    // 11) down_proj + residual -> out
    gemm_h<<<gemm_grid(DM), 256, GSMEM_DYN>>>(uph, downh, h, out, nullptr, DM, INTERD, 1);
}

// round 16
// speedup vs baseline: 1.0187x; 1.0187x over previous
#include <cuda_runtime.h>
#include <cuda_fp16.h>
#include <math.h>
#include <stdint.h>

// ---------------- fixed shapes ----------------
#define TKN   4096
#define NB    2
#define LSEQ  2048
#define DM    4096
#define DXB   1024
#define DIN   4096
#define NH    32
#define HP    128
#define HN    128
#define PROJ  10272
#define CONVD 6144
#define INTERD 14336
#define NCH   16
#define NBLK  (NB*NCH*NH)

// ---------------- scratch ----------------
__device__ __half d_hnormh[TKN*DM];
__device__ float  d_zx[TKN*PROJ];
__device__ float  d_xbc[TKN*CONVD];
__device__ float  d_dt[TKN*NH];
__device__ float  d_av[TKN*NH];
__device__ float  d_cs[NBLK*128];
__device__ float  d_gm[NBLK];
__device__ float  d_states[(size_t)NBLK*HP*HN];
__device__ float  d_prev[(size_t)NBLK*HP*HN];
__device__ __half d_Ydh[TKN*DIN];
__device__ __half d_Yh[TKN*DIN];
__device__ float  d_h[TKN*DM];
__device__ __half d_h2h[TKN*DM];
__device__ __half d_uph[(size_t)TKN*INTERD];
// fp16 weights
__device__ __half d_win_h[(size_t)PROJ*DM];
__device__ __half d_wout_h[(size_t)DM*DIN];
__device__ __half d_gu_h[(size_t)2*INTERD*DM];   // row-interleaved gate/up
__device__ __half d_down_h[(size_t)DM*INTERD];

static __device__ __forceinline__ float tf32r(float x) {
    uint32_t u; asm("cvt.rna.tf32.f32 %0, %1;" : "=r"(u) : "f"(x));
    return __uint_as_float(u);
}

// ---------------- convert weights fp32 -> fp16 ----------------
__global__ void to_half_k(const float* __restrict__ src, __half* __restrict__ dst, int n4)
{
    int stride = gridDim.x * blockDim.x;
    for (int i = blockIdx.x*blockDim.x + threadIdx.x; i < n4; i += stride) {
        float4 v = reinterpret_cast<const float4*>(src)[i];
        reinterpret_cast<__half2*>(dst)[2*i]   = __floats2half2_rn(v.x, v.y);
        reinterpret_cast<__half2*>(dst)[2*i+1] = __floats2half2_rn(v.z, v.w);
    }
}

// ---------------- interleave gate/up rows -> fp16 (even=gate, odd=up) ----------------
__global__ void interleave_half_k(const float* __restrict__ g, const float* __restrict__ u,
                                  __half* __restrict__ dst, int n4)
{
    int stride = gridDim.x * blockDim.x;
    for (int i = blockIdx.x*blockDim.x + threadIdx.x; i < n4; i += stride) {
        int r  = i >> 10;             // DM/4 = 1024 float4 per row
        int c4 = i & 1023;
        const float* src = ((r & 1) ? u : g) + (size_t)(r >> 1)*DM + c4*4;
        float4 v = *reinterpret_cast<const float4*>(src);
        __half* drow = dst + (size_t)r*DM + c4*4;
        *reinterpret_cast<__half2*>(drow)     = __floats2half2_rn(v.x, v.y);
        *reinterpret_cast<__half2*>(drow + 2) = __floats2half2_rn(v.z, v.w);
    }
}

// ---------- tf32 mma tile helpers (SSD path, proven) ----------
static __device__ __forceinline__ uint32_t swaddr(uint32_t base, int r, int c) {
    uint32_t sub   = (uint32_t)((c >> 5) << 14);
    uint32_t chunk = (uint32_t)(((((c & 31) >> 2)) ^ (r & 7)) << 4);
    uint32_t byte  = (uint32_t)((c & 3) << 2);
    return base + sub + (uint32_t)(r << 7) + chunk + byte;
}
static __device__ __forceinline__ void load_tile128(uint32_t sb, const float* g,
                                                    int grs, int tid) {
    #pragma unroll
    for (int i = 0; i < 16; i++) {
        int idx = i*256 + tid;
        int r = idx >> 5, c = (idx & 31) << 2;
        asm volatile("cp.async.cg.shared.global [%0], [%1], 16;"
                     :: "r"(swaddr(sb, r, c)), "l"(g + (size_t)r*grs + c));
    }
}
static __device__ __forceinline__ void mma_tile128(uint32_t abase, uint32_t bbase,
                                                   float (&acc)[4][4][4],
                                                   int wm, int wn, int lane) {
    #pragma unroll
    for (int t = 0; t < 4; t++) {
        uint32_t as = abase + (uint32_t)(t << 14), bs = bbase + (uint32_t)(t << 14);
        #pragma unroll
        for (int kk = 0; kk < 4; kk++) {
            uint32_t af[4][4];
            #pragma unroll
            for (int mt = 0; mt < 4; mt++) {
                int m  = wm*64 + mt*16 + (lane & 7) + ((lane >> 3) & 1) * 8;
                int kc = kk*2 + (lane >> 4);
                uint32_t addr = as + (uint32_t)(m << 7) + (uint32_t)((kc ^ (m & 7)) << 4);
                asm volatile("ldmatrix.sync.aligned.m8n8.x4.shared.b16 {%0,%1,%2,%3}, [%4];"
                             : "=r"(af[mt][0]), "=r"(af[mt][1]),
                               "=r"(af[mt][2]), "=r"(af[mt][3]) : "r"(addr));
            }
            #pragma unroll
            for (int nt = 0; nt < 4; nt++) {
                int nrow = wn*32 + nt*8 + (lane & 7);
                int bc = kk*2 + ((lane >> 3) & 1);
                uint32_t baddr = bs + (uint32_t)(nrow << 7) + (uint32_t)((bc ^ (nrow & 7)) << 4);
                uint32_t b0, b1;
                asm volatile("ldmatrix.sync.aligned.m8n8.x2.shared.b16 {%0,%1}, [%2];"
                             : "=r"(b0), "=r"(b1) : "r"(baddr));
                #pragma unroll
                for (int mt = 0; mt < 4; mt++) {
                    asm volatile(
                        "mma.sync.aligned.m16n8k8.row.col.f32.tf32.tf32.f32 "
                        "{%0,%1,%2,%3}, {%4,%5,%6,%7}, {%8,%9}, {%0,%1,%2,%3};"
                        : "+f"(acc[mt][nt][0]), "+f"(acc[mt][nt][1]),
                          "+f"(acc[mt][nt][2]), "+f"(acc[mt][nt][3])
                        : "r"(af[mt][0]), "r"(af[mt][1]), "r"(af[mt][2]), "r"(af[mt][3]),
                          "r"(b0), "r"(b1));
                }
            }
        }
    }
}
static __device__ __forceinline__ void transpose128(uint32_t src, uint32_t dst,
                                                    int warp, int lane) {
    #pragma unroll
    for (int ks = 0; ks < 4; ks++) {
        int k = ks*32 + lane;
        #pragma unroll
        for (int j = 0; j < 16; j++) {
            int p = warp*16 + j;
            float v;
            asm volatile("ld.shared.f32 %0, [%1];" : "=f"(v) : "r"(swaddr(src, k, p)));
            asm volatile("st.shared.f32 [%0], %1;" :: "r"(swaddr(dst, p, k)), "f"(v));
        }
    }
}
static __device__ __forceinline__ void zero_acc(float (&acc)[4][4][4]) {
    #pragma unroll
    for (int a = 0; a < 4; a++)
        #pragma unroll
        for (int b = 0; b < 4; b++)
            #pragma unroll
            for (int c = 0; c < 4; c++) acc[a][b][c] = 0.f;
}

// ================= fp16 mma.sync dense GEMM (128x128, 2 CTA/SM) =================
#define GSTAGE 32768
#define GSMEM_DYN (3*GSTAGE)
#define GROUP_M 16

__global__ void __launch_bounds__(256, 2)
gemm_h(const __half* __restrict__ A, const __half* __restrict__ Bw,
       const float* __restrict__ Res, float* __restrict__ Cf,
       __half* __restrict__ Ch, int N, int K, int mode)
{
    extern __shared__ char smraw[];
    const int tid  = threadIdx.x;
    const int lane = tid & 31, warp = tid >> 5;
    const int wm = warp & 1, wn = warp >> 1;
    const int T = K >> 6;
    uint32_t sbase = (uint32_t)__cvta_generic_to_shared(smraw);

    const int num_pid_n = (N + 127) >> 7;
    int pid = blockIdx.x;
    int npg = GROUP_M * num_pid_n;
    int pid_m = (pid / npg) * GROUP_M + (pid % GROUP_M);
    int pid_n = (pid % npg) / GROUP_M;
    const int bm = pid_m << 7, bn = pid_n << 7;

    auto load_tile = [&](int t) {
        uint32_t s = sbase + (uint32_t)(t % 3) * GSTAGE;
        int k0 = t << 6;
        #pragma unroll
        for (int i = 0; i < 4; i++) {
            int idx = i*256 + tid, row = idx >> 3, c = idx & 7;
            uint32_t dst = s + row*128 + (uint32_t)((c ^ (row & 7)) << 4);
            asm volatile("cp.async.cg.shared.global [%0], [%1], 16;"
                         :: "r"(dst), "l"(A + (size_t)(bm + row)*K + k0 + c*8));
        }
        #pragma unroll
        for (int i = 0; i < 4; i++) {
            int idx = i*256 + tid, row = idx >> 3, c = idx & 7;
            int brow = bn + row; if (brow >= N) brow = N - 1;
            uint32_t dst = s + 16384u + row*128 + (uint32_t)((c ^ (row & 7)) << 4);
            asm volatile("cp.async.cg.shared.global [%0], [%1], 16;"
                         :: "r"(dst), "l"(Bw + (size_t)brow*K + k0 + c*8));
        }
    };

    float acc[4][4][4];
    zero_acc(acc);

    load_tile(0);
    asm volatile("cp.async.commit_group;" ::: "memory");
    load_tile(1);
    asm volatile("cp.async.commit_group;" ::: "memory");

    for (int t = 0; t < T; t++) {
        asm volatile("cp.async.wait_group 1;" ::: "memory");
        __syncthreads();
        if (t + 2 < T) load_tile(t + 2);
        asm volatile("cp.async.commit_group;" ::: "memory");

        uint32_t as = sbase + (uint32_t)(t % 3) * GSTAGE;
        uint32_t bs = as + 16384u;

        #pragma unroll
        for (int kk = 0; kk < 4; kk++) {
            uint32_t af[4][4];
            #pragma unroll
            for (int mt = 0; mt < 4; mt++) {
                int m  = wm*64 + mt*16 + (lane & 7) + ((lane >> 3) & 1) * 8;
                int kc = kk*2 + (lane >> 4);
                uint32_t addr = as + m*128 + (uint32_t)((kc ^ (m & 7)) << 4);
                asm volatile("ldmatrix.sync.aligned.m8n8.x4.shared.b16 {%0,%1,%2,%3}, [%4];"
                             : "=r"(af[mt][0]), "=r"(af[mt][1]),
                               "=r"(af[mt][2]), "=r"(af[mt][3]) : "r"(addr));
            }
            #pragma unroll
            for (int np = 0; np < 2; np++) {
                int ntl  = np*2 + ((lane >> 4) & 1);
                int nrow = wn*32 + ntl*8 + (lane & 7);
                int bc   = kk*2 + ((lane >> 3) & 1);
                uint32_t baddr = bs + nrow*128 + (uint32_t)((bc ^ (nrow & 7)) << 4);
                uint32_t b0, b1, b2, b3;
                asm volatile("ldmatrix.sync.aligned.m8n8.x4.shared.b16 {%0,%1,%2,%3}, [%4];"
                             : "=r"(b0), "=r"(b1), "=r"(b2), "=r"(b3) : "r"(baddr));
                #pragma unroll
                for (int mt = 0; mt < 4; mt++) {
                    asm volatile(
                        "mma.sync.aligned.m16n8k16.row.col.f32.f16.f16.f32 "
                        "{%0,%1,%2,%3}, {%4,%5,%6,%7}, {%8,%9}, {%0,%1,%2,%3};"
                        : "+f"(acc[mt][np*2][0]), "+f"(acc[mt][np*2][1]),
                          "+f"(acc[mt][np*2][2]), "+f"(acc[mt][np*2][3])
                        : "r"(af[mt][0]), "r"(af[mt][1]), "r"(af[mt][2]), "r"(af[mt][3]),
                          "r"(b0), "r"(b1));
                }
                #pragma unroll
                for (int mt = 0; mt < 4; mt++) {
                    asm volatile(
                        "mma.sync.aligned.m16n8k16.row.col.f32.f16.f16.f32 "
                        "{%0,%1,%2,%3}, {%4,%5,%6,%7}, {%8,%9}, {%0,%1,%2,%3};"
                        : "+f"(acc[mt][np*2+1][0]), "+f"(acc[mt][np*2+1][1]),
                          "+f"(acc[mt][np*2+1][2]), "+f"(acc[mt][np*2+1][3])
                        : "r"(af[mt][0]), "r"(af[mt][1]), "r"(af[mt][2]), "r"(af[mt][3]),
                          "r"(b2), "r"(b3));
                }
            }
        }
    }

    // epilogue
    #pragma unroll
    for (int mt = 0; mt < 4; mt++) {
        int r0 = bm + wm*64 + mt*16 + (lane >> 2);
        #pragma unroll
        for (int nt = 0; nt < 4; nt++) {
            int c0 = bn + wn*32 + nt*8 + 2*(lane & 3);
            if (c0 < N) {
                float2 v0 = make_float2(acc[mt][nt][0], acc[mt][nt][1]);
                float2 v1 = make_float2(acc[mt][nt][2], acc[mt][nt][3]);
                if (mode == 3) {
                    float r0v = v0.y * (v0.x / (1.f + expf(-v0.x)));
                    float r1v = v1.y * (v1.x / (1.f + expf(-v1.x)));
                    int half_n = N >> 1;
                    Ch[(size_t)r0*half_n + (c0 >> 1)]     = __float2half_rn(r0v);
                    Ch[(size_t)(r0+8)*half_n + (c0 >> 1)] = __float2half_rn(r1v);
                } else {
                    if (mode == 1) {
                        float2 q0 = *reinterpret_cast<const float2*>(Res + (size_t)r0*N + c0);
                        float2 q1 = *reinterpret_cast<const float2*>(Res + (size_t)(r0+8)*N + c0);
                        v0.x += q0.x; v0.y += q0.y; v1.x += q1.x; v1.y += q1.y;
                    }
                    *reinterpret_cast<float2*>(Cf + (size_t)r0*N + c0)     = v0;
                    *reinterpret_cast<float2*>(Cf + (size_t)(r0+8)*N + c0) = v1;
                }
            }
        }
    }
}

static inline int gemm_grid(int N) { return 32 * ((N + 127) >> 7); }

// ---------------- RMSNorm (fp16 output) ----------------
__global__ void rmsnorm_k(const float* __restrict__ x, const float* __restrict__ w,
                          __half* __restrict__ o)
{
    int t = blockIdx.x;
    const float* xr = x + (size_t)t*DM;
    float s = 0.f;
    for (int i = threadIdx.x; i < DM; i += 256) { float v = xr[i]; s += v*v; }
    __shared__ float red[256];
    red[threadIdx.x] = s; __syncthreads();
    for (int st = 128; st > 0; st >>= 1) {
        if (threadIdx.x < st) red[threadIdx.x] += red[threadIdx.x + st];
        __syncthreads();
    }
    float inv = rsqrtf(red[0] / (float)DM + 1e-5f);
    __half* orow = o + (size_t)t*DM;
    for (int i = threadIdx.x; i < DM; i += 256) orow[i] = __float2half_rn(xr[i]*inv*w[i]);
}

// ---------------- fused conv+SiLU (4 tokens/thread, register reuse) + dt ----------------
// grid: (25, TKN/4). blockIdx.x<24: conv channels; ==24: dt for 4 tokens.
__global__ void convdt_k(const float* __restrict__ zx, const float* __restrict__ cw,
                         const float* __restrict__ cb, const float* __restrict__ dtb,
                         const float* __restrict__ Alog,
                         float* __restrict__ xbc, float* __restrict__ dto,
                         float* __restrict__ ao)
{
    int t0 = blockIdx.y << 2;                 // multiple of 4
    if (blockIdx.x < 24) {
        int c = blockIdx.x*256 + threadIdx.x; // < 6144
        int l0 = t0 & (LSEQ - 1);             // multiple of 4
        const float* base = zx + (size_t)t0*PROJ + 4096 + c;
        float w0 = cw[c*4+0], w1 = cw[c*4+1], w2 = cw[c*4+2], w3 = cw[c*4+3];
        float cbc = cb[c];
        // sliding window x[t0-3 .. t0+3]; zeros before sequence start
        float xv[7];
        #pragma unroll
        for (int j = 0; j < 7; j++) {
            int ll = l0 - 3 + j;
            xv[j] = (ll >= 0) ? base[(ptrdiff_t)(j - 3)*PROJ] : 0.f;
        }
        float* orow = xbc + (size_t)t0*CONVD + c;
        #pragma unroll
        for (int i = 0; i < 4; i++) {
            // token t0+i uses xv[i]=x[t-3] .. xv[i+3]=x[t]; same op order as before
            float acc = cbc + w3*xv[i+3];
            acc += w2*xv[i+2];
            acc += w1*xv[i+1];
            acc += w0*xv[i];
            float sv = acc / (1.f + expf(-acc));
            orow[(size_t)i*CONVD] = tf32r(sv);
        }
    } else if (threadIdx.x < 128) {
        int t = t0 + (threadIdx.x >> 5);
        int h = threadIdx.x & 31;
        float raw = zx[(size_t)t*PROJ + 10240 + h] + dtb[h];
        float dt = (raw > 20.f) ? raw : log1pf(expf(raw));
        dto[t*NH + h] = dt;
        ao[t*NH + h]  = -expf(Alog[h]) * dt;
    }
}

// ---------------- SSD stage 1 (tf32 tensor cores) ----------------
#define SSD1_SMEM 196608
__global__ void __launch_bounds__(256)
ssd1_k(const float* __restrict__ xbc, const float* __restrict__ dtv,
       const float* __restrict__ av, const float* __restrict__ Dv,
       __half* __restrict__ Yd, float* __restrict__ cso,
       float* __restrict__ gmo, float* __restrict__ states)
{
    extern __shared__ float dyn[];
    __shared__ float cs[128], dts[128], wv[128], wsum[4];
    uint32_t sb = (uint32_t)__cvta_generic_to_shared(dyn);
    uint32_t O_C = sb, O_B = sb + 65536u, O_X = sb + 131072u;

    int blk = blockIdx.x;
    int h = blk & 31, ch = (blk >> 5) & 15, b = blk >> 9;
    int t0 = b*LSEQ + ch*128;
    int g  = h >> 2;
    int tid = threadIdx.x, lane = tid & 31, warp = tid >> 5;
    int wm = warp & 1, wn = warp >> 1;

    const float* gC = xbc + (size_t)t0*CONVD + 2048 + h*128;
    const float* gB = xbc + (size_t)t0*CONVD + 1024 + g*128;
    const float* gX = xbc + (size_t)t0*CONVD + g*128;
    load_tile128(O_C, gC, CONVD, tid);
    load_tile128(O_B, gB, CONVD, tid);
    load_tile128(O_X, gX, CONVD, tid);
    asm volatile("cp.async.commit_group;" ::: "memory");

    float v = 0.f;
    if (tid < 128) {
        dts[tid] = dtv[(size_t)(t0+tid)*NH + h];
        v = av[(size_t)(t0+tid)*NH + h];
        #pragma unroll
        for (int off = 1; off < 32; off <<= 1) {
            float n = __shfl_up_sync(0xffffffffu, v, off);
            if (lane >= off) v += n;
        }
        if (lane == 31) wsum[tid >> 5] = v;
    }
    __syncthreads();
    if (tid < 128) {
        float add = 0.f;
        for (int w = 0; w < (tid >> 5); w++) add += wsum[w];
        float c = v + add;
        cs[tid] = c;
        cso[blk*128 + tid] = c;
    }
    __syncthreads();
    if (tid < 128) wv[tid] = __expf(cs[127] - cs[tid]) * dts[tid];
    if (tid == 0) gmo[blk] = expf(cs[127]);

    asm volatile("cp.async.wait_group 0;" ::: "memory");
    __syncthreads();

    float acc[4][4][4];
    zero_acc(acc);
    mma_tile128(O_C, O_B, acc, wm, wn, lane);
    __syncthreads();
    transpose128(O_X, O_C, warp, lane);
    __syncthreads();
    #pragma unroll
    for (int mt = 0; mt < 4; mt++) {
        int r0 = wm*64 + mt*16 + (lane >> 2);
        #pragma unroll
        for (int nt = 0; nt < 4; nt++) {
            int c0 = wn*32 + nt*8 + 2*(lane & 3);
            #pragma unroll
            for (int e = 0; e < 4; e++) {
                int q = r0 + (e >> 1)*8, k = c0 + (e & 1);
                float f = (q >= k) ? __expf(cs[q] - cs[k]) * dts[k] : 0.f;
                float val = tf32r(acc[mt][nt][e] * f);
                asm volatile("st.shared.f32 [%0], %1;" :: "r"(swaddr(O_X, q, k)), "f"(val));
            }
        }
    }
    __syncthreads();
    zero_acc(acc);
    mma_tile128(O_X, O_C, acc, wm, wn, lane);
    float Dh = Dv[h];
    #pragma unroll
    for (int mt = 0; mt < 4; mt++) {
        int r0 = wm*64 + mt*16 + (lane >> 2);
        #pragma unroll
        for (int nt = 0; nt < 4; nt++) {
            int c0 = wn*32 + nt*8 + 2*(lane & 3);
            #pragma unroll
            for (int e = 0; e < 4; e++) {
                int q = r0 + (e >> 1)*8, p = c0 + (e & 1);
                float xv;
                asm volatile("ld.shared.f32 %0, [%1];" : "=f"(xv) : "r"(swaddr(O_C, p, q)));
                Yd[(size_t)(t0+q)*DIN + h*128 + p] = __float2half_rn(acc[mt][nt][e] + Dh*xv);
            }
        }
    }
    __syncthreads();
    transpose128(O_B, O_X, warp, lane);
    #pragma unroll
    for (int ks = 0; ks < 4; ks++) {
        int k = ks*32 + lane;
        float wk = wv[k];
        #pragma unroll
        for (int j = 0; j < 16; j++) {
            int p = warp*16 + j;
            float xv;
            asm volatile("ld.shared.f32 %0, [%1];" : "=f"(xv) : "r"(swaddr(O_C, p, k)));
            xv = tf32r(xv * wk);
            asm volatile("st.shared.f32 [%0], %1;" :: "r"(swaddr(O_C, p, k)), "f"(xv));
        }
    }
    __syncthreads();
    zero_acc(acc);
    mma_tile128(O_C, O_X, acc, wm, wn, lane);
    size_t sbase = (size_t)blk*HP*HN;
    #pragma unroll
    for (int mt = 0; mt < 4; mt++) {
        int r0 = wm*64 + mt*16 + (lane >> 2);
        #pragma unroll
        for (int nt = 0; nt < 4; nt++) {
            int c0 = wn*32 + nt*8 + 2*(lane & 3);
            *reinterpret_cast<float2*>(states + sbase + (size_t)r0*HN + c0)
                = make_float2(acc[mt][nt][0], acc[mt][nt][1]);
            *reinterpret_cast<float2*>(states + sbase + (size_t)(r0+8)*HN + c0)
                = make_float2(acc[mt][nt][2], acc[mt][nt][3]);
        }
    }
}

// ---------------- inter-chunk recurrence (16 slices per (b,h) for occupancy) ----------------
__global__ void scan_k(const float* __restrict__ states, const float* __restrict__ gm,
                       float* __restrict__ prev)
{
    int bid = blockIdx.x;               // 0..1023
    int bh = bid >> 4, slice = bid & 15;
    int b = bh >> 5, h = bh & 31;
    int e0 = slice*1024 + threadIdx.x;  // 256 threads, 4 elems each
    float S[4];
    #pragma unroll
    for (int e = 0; e < 4; e++) S[e] = 0.f;
    for (int ch = 0; ch < NCH; ch++) {
        int blk = (b*NCH + ch)*NH + h;
        float gv = gm[blk];
        size_t base = (size_t)blk*HP*HN;
        #pragma unroll
        for (int e = 0; e < 4; e++) {
            int idx = e0 + e*256;
            prev[base + idx] = tf32r(S[e]);
            S[e] = gv*S[e] + states[base + idx];
        }
    }
}

// ---------------- SSD stage 2 (tf32 tensor cores) + gating -> fp16 Yh ----------------
#define SSD2_SMEM 131072
__global__ void __launch_bounds__(256)
ssd2_k(const float* __restrict__ xbc, const float* __restrict__ prev,
       const float* __restrict__ csv, const float* __restrict__ zx,
       const __half* __restrict__ Yd, __half* __restrict__ Yh)
{
    extern __shared__ float dyn[];
    __shared__ float cs[128];
    uint32_t sb = (uint32_t)__cvta_generic_to_shared(dyn);
    uint32_t O_C = sb, O_P = sb + 65536u;

    int blk = blockIdx.x;
    int h = blk & 31, ch = (blk >> 5) & 15, b = blk >> 9;
    int t0 = b*LSEQ + ch*128;
    int tid = threadIdx.x, lane = tid & 31, warp = tid >> 5;
    int wm = warp & 1, wn = warp >> 1;

    const float* gC = xbc + (size_t)t0*CONVD + 2048 + h*128;
    size_t pbase = (size_t)blk*HP*HN;
    load_tile128(O_C, gC, CONVD, tid);
    load_tile128(O_P, prev + pbase, HN, tid);
    asm volatile("cp.async.commit_group;" ::: "memory");
    if (tid < 128) cs[tid] = csv[blk*128 + tid];
    asm volatile("cp.async.wait_group 0;" ::: "memory");
    __syncthreads();

    float acc[4][4][4];
    zero_acc(acc);
    mma_tile128(O_C, O_P, acc, wm, wn, lane);

    #pragma unroll
    for (int mt = 0; mt < 4; mt++) {
        int r0 = wm*64 + mt*16 + (lane >> 2);
        float eq0 = __expf(cs[r0]), eq1 = __expf(cs[r0 + 8]);
        #pragma unroll
        for (int nt = 0; nt < 4; nt++) {
            int c0 = wn*32 + nt*8 + 2*(lane & 3);
            #pragma unroll
            for (int half = 0; half < 2; half++) {
                int q = r0 + half*8;
                float eq = half ? eq1 : eq0;
                size_t off = (size_t)(t0+q)*DIN + h*128 + c0;
                __half2 ydh = *reinterpret_cast<const __half2*>(Yd + off);
                float2 yv = __half22float2(ydh);
                float2 zv = *reinterpret_cast<const float2*>(zx + (size_t)(t0+q)*PROJ + h*128 + c0);
                float s0 = zv.x / (1.f + expf(-zv.x));
                float s1 = zv.y / (1.f + expf(-zv.y));
                float a0 = acc[mt][nt][half*2+0], a1 = acc[mt][nt][half*2+1];
                *reinterpret_cast<__half2*>(Yh + off)
                    = __floats2half2_rn((yv.x + eq*a0) * s0, (yv.y + eq*a1) * s1);
            }
        }
    }
}

// ---------------- launcher ----------------
extern "C" void kernel_launch(void* const* d_in, const int* in_sizes, int n_in,
                              void* d_out, int out_size)
{
    const float* hidden = (const float*)d_in[0];
    const float* w_in   = (const float*)d_in[1];
    const float* conv_w = (const float*)d_in[2];
    const float* conv_b = (const float*)d_in[3];
    const float* A_log  = (const float*)d_in[4];
    const float* Dv     = (const float*)d_in[5];
    const float* dt_b   = (const float*)d_in[6];
    const float* w_out  = (const float*)d_in[7];
    const float* ln1    = (const float*)d_in[8];
    const float* ln2    = (const float*)d_in[9];
    const float* gate_w = (const float*)d_in[10];
    const float* up_w   = (const float*)d_in[11];
    const float* down_w = (const float*)d_in[12];
    float* out = (float*)d_out;

    float *zx, *xbc, *dt, *av, *cs, *gm, *st, *pv, *h;
    __half *hnormh, *Ydh, *Yh, *h2h, *uph;
    __half *winh, *wouth, *guh, *downh;
    cudaGetSymbolAddress((void**)&hnormh, d_hnormh);
    cudaGetSymbolAddress((void**)&zx,     d_zx);
    cudaGetSymbolAddress((void**)&xbc,    d_xbc);
    cudaGetSymbolAddress((void**)&dt,     d_dt);
    cudaGetSymbolAddress((void**)&av,     d_av);
    cudaGetSymbolAddress((void**)&cs,     d_cs);
    cudaGetSymbolAddress((void**)&gm,     d_gm);
    cudaGetSymbolAddress((void**)&st,     d_states);
    cudaGetSymbolAddress((void**)&pv,     d_prev);
    cudaGetSymbolAddress((void**)&Ydh,    d_Ydh);
    cudaGetSymbolAddress((void**)&Yh,     d_Yh);
    cudaGetSymbolAddress((void**)&h,      d_h);
    cudaGetSymbolAddress((void**)&h2h,    d_h2h);
    cudaGetSymbolAddress((void**)&uph,    d_uph);
    cudaGetSymbolAddress((void**)&winh,   d_win_h);
    cudaGetSymbolAddress((void**)&wouth,  d_wout_h);
    cudaGetSymbolAddress((void**)&guh,    d_gu_h);
    cudaGetSymbolAddress((void**)&downh,  d_down_h);

    cudaFuncSetAttribute(gemm_h, cudaFuncAttributeMaxDynamicSharedMemorySize, GSMEM_DYN);
    cudaFuncSetAttribute(ssd1_k, cudaFuncAttributeMaxDynamicSharedMemorySize, SSD1_SMEM);
    cudaFuncSetAttribute(ssd2_k, cudaFuncAttributeMaxDynamicSharedMemorySize, SSD2_SMEM);

    // one-time side stream + events
    static cudaStream_t s2 = nullptr;
    static cudaEvent_t e_fork = nullptr, e_win = nullptr, e_join = nullptr;
    static bool side_ok = false;
    if (!s2) {
        side_ok = (cudaStreamCreateWithFlags(&s2, cudaStreamNonBlocking) == cudaSuccess)
               && (cudaEventCreateWithFlags(&e_fork, cudaEventDisableTiming) == cudaSuccess)
               && (cudaEventCreateWithFlags(&e_win,  cudaEventDisableTiming) == cudaSuccess)
               && (cudaEventCreateWithFlags(&e_join, cudaEventDisableTiming) == cudaSuccess);
    }

    if (side_ok) {
        cudaEventRecord(e_fork, 0);
        cudaStreamWaitEvent(s2, e_fork, 0);
        to_half_k<<<1024, 256, 0, s2>>>(w_in, winh, (PROJ*DM)/4);
        cudaEventRecord(e_win, s2);
        to_half_k<<<1024, 256, 0, s2>>>(w_out,  wouth, (DM*DIN)/4);
        interleave_half_k<<<2048, 256, 0, s2>>>(gate_w, up_w, guh, (2*INTERD*DM)/4);
        to_half_k<<<1024, 256, 0, s2>>>(down_w, downh, (DM*INTERD)/4);
        cudaEventRecord(e_join, s2);
        rmsnorm_k<<<TKN, 256>>>(hidden, ln1, hnormh);
        cudaStreamWaitEvent(0, e_win, 0);
    } else {
        to_half_k<<<1024, 256>>>(w_in,   winh,  (PROJ*DM)/4);
        to_half_k<<<1024, 256>>>(w_out,  wouth, (DM*DIN)/4);
        interleave_half_k<<<2048, 256>>>(gate_w, up_w, guh, (2*INTERD*DM)/4);
        to_half_k<<<1024, 256>>>(down_w, downh, (DM*INTERD)/4);
        rmsnorm_k<<<TKN, 256>>>(hidden, ln1, hnormh);
    }

    // 2) in_proj
    gemm_h<<<gemm_grid(PROJ), 256, GSMEM_DYN>>>(hnormh, winh, nullptr, zx, nullptr, PROJ, DM, 0);
    // 3+4) fused conv (4 tok/thread) + dt
    convdt_k<<<dim3(25, TKN/4), 256>>>(zx, conv_w, conv_b, dt_b, A_log, xbc, dt, av);
    // 5) SSD stage 1 (tf32 tensor cores) -> Yd fp16
    ssd1_k<<<NBLK, 256, SSD1_SMEM>>>(xbc, dt, av, Dv, Ydh, cs, gm, st);
    // 6) inter-chunk recurrence (16x occupancy)
    scan_k<<<NB*NH*16, 256>>>(st, gm, pv);
    // 7) SSD stage 2 + gating -> fp16 Yh
    ssd2_k<<<NBLK, 256, SSD2_SMEM>>>(xbc, pv, cs, zx, Ydh, Yh);

    if (side_ok) cudaStreamWaitEvent(0, e_join, 0);

    // 8) out_proj + residual
    gemm_h<<<gemm_grid(DM), 256, GSMEM_DYN>>>(Yh, wouth, hidden, h, nullptr, DM, DIN, 1);
    // 9) second norm (fp16 output)
    rmsnorm_k<<<TKN, 256>>>(h, ln2, h2h);
    // 10) fused gate+up GEMM -> uph = silu(gate)*up (fp16)
    gemm_h<<<gemm_grid(2*INTERD), 256, GSMEM_DYN>>>(h2h, guh, nullptr, nullptr, uph,
                                                    2*INTERD, DM, 3);
    // 11) down_proj + residual -> out
    gemm_h<<<gemm_grid(DM), 256, GSMEM_DYN>>>(uph, downh, h, out, nullptr, DM, INTERD, 1);
}